// round 2
// baseline (speedup 1.0000x reference)
#include <cuda_runtime.h>
#include <cuda_bf16.h>

// Problem constants (from reference)
#define Bq 128
#define Nq 36
#define Dq 512
#define Gq 2
#define NEGV -1e10f

// One block per batch element. 512 threads (16 warps).
// logits factorization:
//   logits[b,n,g] = sum_d o[n,d]^2 * SW[g,d] - sum_d o[n,d] * T[b,g,d]
//   SW[g,d] = sum_m W[g,m,d],  T[b,g,d] = sum_m W[g,m,d]*o[b,m,d]
__global__ __launch_bounds__(512, 2)
void qgen_attn_kernel(const float* __restrict__ obj,   // [B, N, D]
                      const float* __restrict__ W,     // [G, N*D]
                      const float* __restrict__ bias,  // [G]
                      const unsigned char* __restrict__ mask_bytes, // [B,N] bool OR int32
                      float* __restrict__ out)         // [B, G*D]
{
    __shared__ float T_s[Gq * Dq];      // 4 KB
    __shared__ float SW_s[Gq * Dq];     // 4 KB
    __shared__ float logit_s[Nq * Gq];  // 288 B
    __shared__ float weight_s[Nq * Gq]; // 288 B
    __shared__ int   nonzero_offbyte;   // mask dtype detection

    const int b   = blockIdx.x;
    const int tid = threadIdx.x;   // 0..511
    const int d   = tid;

    if (tid == 0) nonzero_offbyte = 0;
    __syncthreads();

    // ---- Mask dtype detection ----
    // If mask is int32 (values 0/1, little-endian), every byte at offset j%4!=0
    // is zero. If mask is uint8 (random 0/1), some of these 192 bytes are 1
    // with overwhelming probability. Reading 256 bytes is in-bounds for both
    // interpretations (uint8 buffer = 4608 B, int32 buffer = 18432 B).
    if (tid < 256 && (tid & 3) != 0) {
        if (mask_bytes[tid] != 0) atomicOr(&nonzero_offbyte, 1);
    }

    const float* __restrict__ objb = obj + (size_t)b * Nq * Dq;

    // ---- Phase 1: SW and T (coalesced W + obj reads; obj lands in L1) ----
    #pragma unroll
    for (int g = 0; g < Gq; g++) {
        const float* __restrict__ Wg = W + (size_t)g * Nq * Dq + d;
        float sw = 0.f, t = 0.f;
        #pragma unroll
        for (int m = 0; m < Nq; m++) {
            float w = __ldg(Wg + m * Dq);
            float o = __ldg(objb + m * Dq + d);
            sw += w;
            t  = fmaf(w, o, t);
        }
        SW_s[g * Dq + d] = sw;
        T_s [g * Dq + d] = t;
    }
    __syncthreads();

    const bool mask_is_i32 = (nonzero_offbyte == 0);

    // ---- Phase 2: logits[n,g] = sum_d o*(o*SW - T) + bias ----
    const int warp = tid >> 5;
    const int lane = tid & 31;
    for (int p = warp; p < Nq * Gq; p += 16) {
        const int n = p >> 1;       // p = n*G + g (G == 2)
        const int g = p & 1;
        const float* __restrict__ on  = objb + n * Dq;
        const float* __restrict__ swg = SW_s + g * Dq;
        const float* __restrict__ tg  = T_s  + g * Dq;
        float acc = 0.f;
        #pragma unroll 4
        for (int dd = lane; dd < Dq; dd += 32) {
            float o = __ldg(on + dd);
            acc = fmaf(o, fmaf(o, swg[dd], -tg[dd]), acc);
        }
        #pragma unroll
        for (int off = 16; off > 0; off >>= 1)
            acc += __shfl_down_sync(0xffffffffu, acc, off);
        if (lane == 0) logit_s[p] = acc + __ldg(bias + g);
    }
    __syncthreads();

    // ---- Phase 3: masked softmax over n (per g); warps 0..1 ----
    if (warp < Gq) {
        const int g = warp;
        const int n0 = lane, n1 = lane + 32;
        bool v0 = false, v1 = false;
        if (mask_is_i32) {
            const int* mi = (const int*)mask_bytes;
            if (n0 < Nq) v0 = mi[b * Nq + n0] != 0;
            if (n1 < Nq) v1 = mi[b * Nq + n1] != 0;
        } else {
            if (n0 < Nq) v0 = mask_bytes[b * Nq + n0] != 0;
            if (n1 < Nq) v1 = mask_bytes[b * Nq + n1] != 0;
        }
        float x0 = -1e30f, x1 = -1e30f;
        if (n0 < Nq) x0 = v0 ? logit_s[n0 * Gq + g] : NEGV;
        if (n1 < Nq) x1 = v1 ? logit_s[n1 * Gq + g] : NEGV;
        float mx = fmaxf(x0, x1);
        #pragma unroll
        for (int off = 16; off > 0; off >>= 1)
            mx = fmaxf(mx, __shfl_xor_sync(0xffffffffu, mx, off));
        float e0 = (n0 < Nq) ? __expf(x0 - mx) : 0.f;
        float e1 = (n1 < Nq) ? __expf(x1 - mx) : 0.f;
        float s = e0 + e1;
        #pragma unroll
        for (int off = 16; off > 0; off >>= 1)
            s += __shfl_xor_sync(0xffffffffu, s, off);
        const float inv = 1.f / s;
        if (n0 < Nq) weight_s[n0 * Gq + g] = e0 * inv;
        if (n1 < Nq) weight_s[n1 * Gq + g] = e1 * inv;
    }
    __syncthreads();

    // ---- Phase 4: vis[g,d] = sum_n weight[n,g] * obj[n,d]; write [B, G*D] ----
    #pragma unroll
    for (int g = 0; g < Gq; g++) {
        float acc = 0.f;
        #pragma unroll
        for (int n = 0; n < Nq; n++)
            acc = fmaf(weight_s[n * Gq + g], __ldg(objb + n * Dq + d), acc);
        out[(size_t)b * Gq * Dq + g * Dq + d] = acc;
    }
}

extern "C" void kernel_launch(void* const* d_in, const int* in_sizes, int n_in,
                              void* d_out, int out_size) {
    const float*         obj  = (const float*)d_in[0];         // [128, 36, 512]
    const float*         W    = (const float*)d_in[1];         // [2, 36*512]
    const float*         bias = (const float*)d_in[2];         // [2]
    const unsigned char* mask = (const unsigned char*)d_in[3]; // [128, 36] bool/int32
    float* out = (float*)d_out;                                // [128, 1024]

    qgen_attn_kernel<<<Bq, Dq>>>(obj, W, bias, mask, out);
}

// round 3
// speedup vs baseline: 1.1910x; 1.1910x over previous
#include <cuda_runtime.h>
#include <cuda_bf16.h>

// Problem constants (from reference)
#define Bq 128
#define Nq 36
#define Dq 512
#define Gq 2
#define NDq (Nq * Dq)
#define NEGV -1e10f

// One block per batch element, 1024 threads (32 warps).
// tid = g*512 + d : each thread owns one (g,d) pair.
// logits factorization:
//   logits[b,n,g] = sum_d o[n,d]^2 * SW[g,d] - sum_d o[n,d] * T[b,g,d]
//   SW[g,d] = sum_m W[g,m,d],  T[b,g,d] = sum_m W[g,m,d]*o[b,m,d]
__global__ __launch_bounds__(1024, 1)
void qgen_attn_kernel(const float* __restrict__ obj,   // [B, N, D]
                      const float* __restrict__ W,     // [G, N*D]
                      const float* __restrict__ bias,  // [G]
                      const unsigned char* __restrict__ mask_bytes, // [B,N] int32/bool
                      float* __restrict__ out)         // [B, G*D]
{
    __shared__ __align__(16) float T_s[Gq * Dq];   // 4 KB
    __shared__ __align__(16) float SW_s[Gq * Dq];  // 4 KB
    __shared__ float logit_s[Nq * Gq];             // 288 B
    __shared__ float weight_s[Nq * Gq];            // 288 B
    __shared__ int   nonzero_offbyte;

    const int b   = blockIdx.x;
    const int tid = threadIdx.x;      // 0..1023
    const int g   = tid >> 9;         // 0..1
    const int d   = tid & 511;        // 0..511

    if (tid == 0) nonzero_offbyte = 0;
    __syncthreads();

    // ---- Mask dtype detection (int32 => all bytes at offset%4!=0 are zero) ----
    if (tid < 256 && (tid & 3) != 0) {
        if (mask_bytes[tid] != 0) atomicOr(&nonzero_offbyte, 1);
    }

    const float* __restrict__ objb = obj + (size_t)b * NDq;

    // ---- Phase 1: SW[g,d], T[g,d]; one g per thread ----
    {
        const float* __restrict__ Wg = W + (size_t)g * NDq + d;
        float sw = 0.f, t = 0.f;
        #pragma unroll
        for (int m = 0; m < Nq; m++) {
            float w = __ldg(Wg + m * Dq);
            float o = __ldg(objb + m * Dq + d);
            sw += w;
            t  = fmaf(w, o, t);
        }
        SW_s[g * Dq + d] = sw;
        T_s [g * Dq + d] = t;
    }
    __syncthreads();

    const bool mask_is_i32 = (nonzero_offbyte == 0);
    const int warp = tid >> 5;
    const int lane = tid & 31;

    // ---- Phase 2: logits[n,g] = sum_d o*(o*SW - T) + bias; 72 tasks / 32 warps ----
    for (int p = warp; p < Nq * Gq; p += 32) {
        const int n  = p >> 1;
        const int gg = p & 1;
        const float4* __restrict__ on4 = (const float4*)(objb + n * Dq);
        const float4* __restrict__ sw4 = (const float4*)(SW_s + gg * Dq);
        const float4* __restrict__ tg4 = (const float4*)(T_s  + gg * Dq);
        float acc = 0.f;
        #pragma unroll
        for (int k = 0; k < 4; k++) {
            const int i = k * 32 + lane;
            float4 o  = __ldg(on4 + i);
            float4 s  = sw4[i];
            float4 tt = tg4[i];
            acc = fmaf(o.x, fmaf(o.x, s.x, -tt.x), acc);
            acc = fmaf(o.y, fmaf(o.y, s.y, -tt.y), acc);
            acc = fmaf(o.z, fmaf(o.z, s.z, -tt.z), acc);
            acc = fmaf(o.w, fmaf(o.w, s.w, -tt.w), acc);
        }
        #pragma unroll
        for (int off = 16; off > 0; off >>= 1)
            acc += __shfl_down_sync(0xffffffffu, acc, off);
        if (lane == 0) logit_s[p] = acc + __ldg(bias + gg);
    }
    __syncthreads();

    // ---- Phase 3: masked softmax over n; warp 0 -> g=0, warp 16 -> g=1 ----
    if ((warp & 15) == 0) {
        const int gg = warp >> 4;
        const int n0 = lane, n1 = lane + 32;
        bool v0 = false, v1 = false;
        if (mask_is_i32) {
            const int* mi = (const int*)mask_bytes;
            if (n0 < Nq) v0 = mi[b * Nq + n0] != 0;
            if (n1 < Nq) v1 = mi[b * Nq + n1] != 0;
        } else {
            if (n0 < Nq) v0 = mask_bytes[b * Nq + n0] != 0;
            if (n1 < Nq) v1 = mask_bytes[b * Nq + n1] != 0;
        }
        float x0 = -1e30f, x1 = -1e30f;
        if (n0 < Nq) x0 = v0 ? logit_s[n0 * Gq + gg] : NEGV;
        if (n1 < Nq) x1 = v1 ? logit_s[n1 * Gq + gg] : NEGV;
        float mx = fmaxf(x0, x1);
        #pragma unroll
        for (int off = 16; off > 0; off >>= 1)
            mx = fmaxf(mx, __shfl_xor_sync(0xffffffffu, mx, off));
        float e0 = (n0 < Nq) ? __expf(x0 - mx) : 0.f;
        float e1 = (n1 < Nq) ? __expf(x1 - mx) : 0.f;
        float s = e0 + e1;
        #pragma unroll
        for (int off = 16; off > 0; off >>= 1)
            s += __shfl_xor_sync(0xffffffffu, s, off);
        const float inv = 1.f / s;
        if (n0 < Nq) weight_s[n0 * Gq + gg] = e0 * inv;
        if (n1 < Nq) weight_s[n1 * Gq + gg] = e1 * inv;
    }
    __syncthreads();

    // ---- Phase 4: out[b, g*D+d] = sum_n weight[n,g] * obj[n,d] ----
    {
        float acc = 0.f;
        #pragma unroll
        for (int n = 0; n < Nq; n++)
            acc = fmaf(weight_s[n * Gq + g], __ldg(objb + n * Dq + d), acc);
        out[(size_t)b * (Gq * Dq) + g * Dq + d] = acc;
    }
}

extern "C" void kernel_launch(void* const* d_in, const int* in_sizes, int n_in,
                              void* d_out, int out_size) {
    const float*         obj  = (const float*)d_in[0];         // [128, 36, 512]
    const float*         W    = (const float*)d_in[1];         // [2, 36*512]
    const float*         bias = (const float*)d_in[2];         // [2]
    const unsigned char* mask = (const unsigned char*)d_in[3]; // [128, 36]
    float* out = (float*)d_out;                                // [128, 1024]

    qgen_attn_kernel<<<Bq, 1024>>>(obj, W, bias, mask, out);
}